// round 1
// baseline (speedup 1.0000x reference)
#include <cuda_runtime.h>
#include <cstdint>
#include <cstddef>

#define NUK 2048
#define NVK 2048
#define RNC 5
#define DIMK 128
#define H0K 64
#define H1K 32
#define NUSERS 6040
#define NITEMS 3706
#define ROWP 3712

// ---------------- scratch (static device memory; no allocations) ----------------
__device__ float d_sup[RNC * 4096 * H0K];       // sup[r][n][h]
__device__ float d_du[NVK];                      // per-v degree (summed over u,r)
__device__ float d_di[NUK];                      // per-u degree
__device__ unsigned char d_code[(size_t)NUK * NVK];   // class code per (u,v), 255 = no obs
__device__ unsigned char d_codeT[(size_t)NVK * NUK];  // transposed
__device__ float d_hidden[4096 * H1K];          // sigmoid output, rows 0..2047 users, 2048.. items
__device__ float d_Q[RNC * H1K * H1K];          // Q[r][d][e]
__device__ float d_gu[NUK * RNC * H1K];         // gu[u][r*32+e]
__device__ float d_acc2[2];                      // loss_sum, rmse_sq_sum

// FMA-pipe exp (avoids MUFU.EX2; ~1e-6 rel err on the range used here)
__device__ __forceinline__ float fexp(float x) {
    float y = x * 1.4426950408889634f;
    float t = y + 12582912.0f;                 // round-to-nearest via magic number
    int   ni = __float_as_int(t) - 0x4B400000; // integer n (works for negative n)
    float n = t - 12582912.0f;
    float f = y - n;                            // f in [-0.5, 0.5]
    float p = 1.3333558e-3f;
    p = fmaf(p, f, 9.6181291e-3f);
    p = fmaf(p, f, 5.5504109e-2f);
    p = fmaf(p, f, 2.4022651e-1f);
    p = fmaf(p, f, 6.9314718e-1f);
    p = fmaf(p, f, 1.0f);
    return p * __int_as_float((ni + 127) << 23);
}

// ---------------- init: zero accumulators ----------------
__global__ void k_init() {
    int t = blockIdx.x * blockDim.x + threadIdx.x;
    if (t < NVK) d_du[t] = 0.f;
    if (t < 2)   d_acc2[t] = 0.f;
}

// ---------------- sup[r][n][h] = sum_d x[n][d] * gcl_w[r][d][h] ----------------
__global__ void k_sup(const int* __restrict__ u, const int* __restrict__ v,
                      const float* __restrict__ ue, const float* __restrict__ ve,
                      const float* __restrict__ w) {
    int n = blockIdx.x;
    __shared__ float xs[DIMK];
    const float* src = (n < NUK) ? (ue + (size_t)u[n] * DIMK)
                                 : (ve + (size_t)v[n - NUK] * DIMK);
    for (int d = threadIdx.x; d < DIMK; d += 64) xs[d] = src[d];
    __syncthreads();
    int h = threadIdx.x;
    #pragma unroll
    for (int r = 0; r < RNC; r++) {
        float acc = 0.f;
        const float* wr = w + (size_t)r * DIMK * H0K + h;
        #pragma unroll 8
        for (int d = 0; d < DIMK; d++) acc = fmaf(xs[d], wr[d * H0K], acc);
        d_sup[((size_t)r * 4096 + n) * H0K + h] = acc;
    }
}

// ---------------- pass A: read m rows once; emit code, du, di ----------------
__global__ void k_passA(const int* __restrict__ u, const int* __restrict__ v,
                        const float* __restrict__ m) {
    extern __shared__ char smemraw[];
    int*   sv   = (int*)smemraw;
    float* rows = (float*)(smemraw + NVK * sizeof(int));
    __shared__ float wred[8];
    int tid = threadIdx.x;
    for (int idx = tid; idx < NVK; idx += 256) sv[idx] = v[idx];

    float du_loc[8];
    #pragma unroll
    for (int k = 0; k < 8; k++) du_loc[k] = 0.f;

    for (int ii = 0; ii < 4; ii++) {
        int i = blockIdx.x * 4 + ii;
        int Ui = u[i];
        __syncthreads();  // sv ready / previous gather done before overwriting rows
        #pragma unroll
        for (int r = 0; r < RNC; r++) {
            const float* src = m + ((size_t)r * NUSERS + Ui) * NITEMS;
            for (int c2 = tid; c2 < NITEMS; c2 += 256) rows[r * ROWP + c2] = src[c2];
        }
        __syncthreads();
        float rowsum = 0.f;
        #pragma unroll
        for (int k = 0; k < 8; k++) {
            int j = tid + k * 256;
            int vj = sv[j];
            float vs = 0.f; int cls = 255;
            #pragma unroll
            for (int r = 0; r < RNC; r++) {
                float mv = rows[r * ROWP + vj];
                vs += mv;
                if (mv > 0.5f) cls = r;
            }
            du_loc[k] += vs; rowsum += vs;
            d_code[(size_t)i * NVK + j] = (unsigned char)cls;
        }
        #pragma unroll
        for (int o = 16; o > 0; o >>= 1) rowsum += __shfl_down_sync(0xffffffffu, rowsum, o);
        if ((tid & 31) == 0) wred[tid >> 5] = rowsum;
        __syncthreads();
        if (tid == 0) {
            float t2 = 0.f;
            #pragma unroll
            for (int wq = 0; wq < 8; wq++) t2 += wred[wq];
            d_di[i] = t2;   // exclusive owner: no atomic needed
        }
    }
    #pragma unroll
    for (int k = 0; k < 8; k++) atomicAdd(&d_du[tid + k * 256], du_loc[k]);
}

// ---------------- transpose code -> codeT (32x32 byte tiles) ----------------
__global__ void k_trans() {
    __shared__ unsigned char t[32][33];
    int x = threadIdx.x & 31, y0 = threadIdx.x >> 5;
    size_t bx = (size_t)blockIdx.x * 32, by = (size_t)blockIdx.y * 32;
    #pragma unroll
    for (int yy = 0; yy < 32; yy += 8)
        t[y0 + yy][x] = d_code[(by + y0 + yy) * NVK + bx + x];
    __syncthreads();
    #pragma unroll
    for (int yy = 0; yy < 32; yy += 8)
        d_codeT[(bx + y0 + yy) * NUK + by + x] = t[x][y0 + yy];
}

// ---------------- rows: out_u/out_v via sparse code, then z->relu->dense->sigmoid ----------------
__global__ void k_rows(const float* __restrict__ gclb, const float* __restrict__ dw,
                       const float* __restrict__ db) {
    int n = blockIdx.x;
    int h = threadIdx.x;  // 64
    __shared__ unsigned char crow[2048];
    __shared__ unsigned short lst[2048];
    __shared__ int scnt;
    __shared__ float zs[H0K];

    const unsigned char* src; int off; float deg;
    if (n < NUK) { src = d_code  + (size_t)n * NVK;        off = NUK; deg = d_du[n]; }
    else         { src = d_codeT + (size_t)(n - NUK) * NUK; off = 0;   deg = d_di[n - NUK]; }
    if (h == 0) scnt = 0;
    for (int idx = h; idx < 2048 / 16; idx += 64)
        ((uint4*)crow)[idx] = ((const uint4*)src)[idx];
    __syncthreads();
    #pragma unroll 4
    for (int b = 0; b < 32; b++) {
        int jj = h * 32 + b;
        unsigned char c = crow[jj];
        if (c < RNC) { int p = atomicAdd(&scnt, 1); lst[p] = (unsigned short)((jj << 3) | c); }
    }
    __syncthreads();
    int cnt = scnt;
    float a0 = 0.f, a1 = 0.f, a2 = 0.f, a3 = 0.f;
    int k = 0;
    for (; k + 4 <= cnt; k += 4) {
        unsigned short e0 = lst[k], e1 = lst[k + 1], e2 = lst[k + 2], e3 = lst[k + 3];
        a0 += d_sup[(((e0 & 7) * 4096) + off + (e0 >> 3)) * H0K + h];
        a1 += d_sup[(((e1 & 7) * 4096) + off + (e1 >> 3)) * H0K + h];
        a2 += d_sup[(((e2 & 7) * 4096) + off + (e2 >> 3)) * H0K + h];
        a3 += d_sup[(((e3 & 7) * 4096) + off + (e3 >> 3)) * H0K + h];
    }
    for (; k < cnt; k++) {
        unsigned short e0 = lst[k];
        a0 += d_sup[(((e0 & 7) * 4096) + off + (e0 >> 3)) * H0K + h];
    }
    float acc = (a0 + a1) + (a2 + a3);
    float ad = fabsf(deg);
    float cinv = (ad > 0.f) ? (1.f / ad) : 0.f;
    float z = fmaf(acc, cinv, 5.f * gclb[h]);
    zs[h] = fmaxf(z, 0.f);
    __syncthreads();
    if (h < H1K) {
        float s = db[h];
        #pragma unroll
        for (int h0 = 0; h0 < H0K; h0++) s = fmaf(zs[h0], dw[h0 * H1K + h], s);
        d_hidden[n * H1K + h] = 1.f / (1.f + fexp(-s));
    }
}

// ---------------- Q[r][d][e] = a[r][0] P[0][d][e] + a[r][1] P[1][d][e] ----------------
__global__ void k_q(const float* __restrict__ P, const float* __restrict__ a) {
    int idx = blockIdx.x * blockDim.x + threadIdx.x;
    if (idx < RNC * H1K * H1K) {
        int r = idx / (H1K * H1K); int de = idx % (H1K * H1K);
        d_Q[idx] = a[2 * r] * P[de] + a[2 * r + 1] * P[H1K * H1K + de];
    }
}

// ---------------- gu[u][r][e] = sum_d hu[u][d] Q[r][d][e] ----------------
__global__ void k_gu() {
    int n = blockIdx.x;
    __shared__ float hs[H1K];
    int t = threadIdx.x;  // 160
    if (t < H1K) hs[t] = d_hidden[n * H1K + t];
    __syncthreads();
    int r = t >> 5, e = t & 31;
    float acc = 0.f;
    #pragma unroll
    for (int d = 0; d < H1K; d++) acc = fmaf(hs[d], d_Q[(r * H1K + d) * H1K + e], acc);
    d_gu[n * 160 + t] = acc;
}

// ---------------- final fused: logits + softmax + m_hat + loss + rmse ----------------
__global__ void __launch_bounds__(256) k_final(float* __restrict__ out) {
    __shared__ float sgu[32 * 160];
    __shared__ float shv[32 * 33];
    __shared__ unsigned char scd[1024];
    __shared__ float red[16];
    int tid = threadIdx.x;
    int ub = blockIdx.y * 32, vb = blockIdx.x * 32;

    for (int idx = tid; idx < 5120; idx += 256) sgu[idx] = d_gu[(size_t)ub * 160 + idx];
    for (int idx = tid; idx < 1024; idx += 256)
        shv[(idx >> 5) * 33 + (idx & 31)] = d_hidden[(size_t)(NUK + vb + (idx >> 5)) * H1K + (idx & 31)];
    {
        int row = tid >> 3, c4 = (tid & 7) * 4;
        *(uchar4*)(scd + row * 32 + c4) = *(const uchar4*)(d_code + (size_t)(ub + row) * NVK + vb + c4);
    }
    __syncthreads();

    int u0 = (tid >> 4) * 2, v0 = (tid & 15) * 2;
    float hva[32], hvb[32];
    #pragma unroll
    for (int e = 0; e < 32; e++) { hva[e] = shv[v0 * 33 + e]; hvb[e] = shv[(v0 + 1) * 33 + e]; }
    float acc[20];
    #pragma unroll
    for (int q = 0; q < 20; q++) acc[q] = 0.f;
    #pragma unroll
    for (int r = 0; r < RNC; r++) {
        int b0 = u0 * 160 + r * 32, b1 = b0 + 160;
        #pragma unroll
        for (int e = 0; e < 32; e++) {
            float g0 = sgu[b0 + e], g1 = sgu[b1 + e];
            acc[r * 4 + 0] = fmaf(g0, hva[e], acc[r * 4 + 0]);
            acc[r * 4 + 1] = fmaf(g0, hvb[e], acc[r * 4 + 1]);
            acc[r * 4 + 2] = fmaf(g1, hva[e], acc[r * 4 + 2]);
            acc[r * 4 + 3] = fmaf(g1, hvb[e], acc[r * 4 + 3]);
        }
    }

    float loss_t = 0.f, rmse_t = 0.f;
    float mh[4];
    #pragma unroll
    for (int p = 0; p < 4; p++) {
        float l0 = acc[p], l1 = acc[4 + p], l2 = acc[8 + p], l3 = acc[12 + p], l4 = acc[16 + p];
        float mx = fmaxf(fmaxf(fmaxf(l0, l1), fmaxf(l2, l3)), l4);
        float e0 = fexp(l0 - mx), e1 = fexp(l1 - mx), e2 = fexp(l2 - mx),
              e3 = fexp(l3 - mx), e4 = fexp(l4 - mx);
        float s = ((e0 + e1) + (e2 + e3)) + e4;
        float num = fmaf(2.f, e1, e0);
        num = fmaf(3.f, e2, num);
        num = fmaf(4.f, e3, num);
        num = fmaf(5.f, e4, num);
        float inv = 1.f / s;          // single MUFU.RCP per pair (hidden under FMA)
        float m_hat = num * inv;
        mh[p] = m_hat;
        int du_ = p >> 1, dv_ = p & 1;
        unsigned char c = scd[(u0 + du_) * 32 + (v0 + dv_)];
        if (c < 5) {
            float lc = l0;
            lc = (c == 1) ? l1 : lc; lc = (c == 2) ? l2 : lc;
            lc = (c == 3) ? l3 : lc; lc = (c == 4) ? l4 : lc;
            loss_t += (mx + __logf(s)) - lc;   // -logp
            float dd = m_hat - (float)(c + 1);
            rmse_t = fmaf(dd, dd, rmse_t);
        }
    }
    {
        size_t base = (size_t)(ub + u0) * NVK + vb + v0;
        *(float2*)(out + base)       = make_float2(mh[0], mh[1]);
        *(float2*)(out + base + NVK) = make_float2(mh[2], mh[3]);
    }
    #pragma unroll
    for (int o = 16; o > 0; o >>= 1) {
        loss_t += __shfl_down_sync(0xffffffffu, loss_t, o);
        rmse_t += __shfl_down_sync(0xffffffffu, rmse_t, o);
    }
    int lane = tid & 31, w = tid >> 5;
    if (lane == 0) { red[w] = loss_t; red[8 + w] = rmse_t; }
    __syncthreads();
    if (tid == 0) {
        float ls = 0.f, rs = 0.f;
        #pragma unroll
        for (int q = 0; q < 8; q++) { ls += red[q]; rs += red[8 + q]; }
        atomicAdd(&d_acc2[0], ls);
        atomicAdd(&d_acc2[1], rs);
    }
}

// ---------------- finalize: cnt = sum(du); write loss & rmse ----------------
__global__ void k_finalize(float* __restrict__ out, int out_size) {
    __shared__ float rd[256];
    float s = 0.f;
    for (int idx = threadIdx.x; idx < NVK; idx += 256) s += d_du[idx];
    rd[threadIdx.x] = s;
    __syncthreads();
    for (int o = 128; o > 0; o >>= 1) {
        if (threadIdx.x < o) rd[threadIdx.x] += rd[threadIdx.x + o];
        __syncthreads();
    }
    if (threadIdx.x == 0) {
        float cnt = fmaxf(rd[0], 1.f);
        out[out_size - 2] = d_acc2[0] / cnt;
        out[out_size - 1] = sqrtf(d_acc2[1] / cnt);
    }
}

extern "C" void kernel_launch(void* const* d_in, const int* in_sizes, int n_in,
                              void* d_out, int out_size) {
    const int*   u       = (const int*)d_in[0];
    const int*   v       = (const int*)d_in[1];
    const float* m       = (const float*)d_in[2];
    const float* u_emb   = (const float*)d_in[3];
    const float* v_emb   = (const float*)d_in[4];
    const float* gcl_w   = (const float*)d_in[5];
    const float* gcl_b   = (const float*)d_in[6];
    const float* dense_w = (const float*)d_in[7];
    const float* dense_b = (const float*)d_in[8];
    const float* P       = (const float*)d_in[9];
    const float* a       = (const float*)d_in[10];
    float* out = (float*)d_out;

    const size_t smemA = NVK * sizeof(int) + (size_t)RNC * ROWP * sizeof(float); // 82432
    cudaFuncSetAttribute(k_passA, cudaFuncAttributeMaxDynamicSharedMemorySize, (int)smemA);

    k_init<<<8, 256>>>();
    k_sup<<<4096, 64>>>(u, v, u_emb, v_emb, gcl_w);
    k_passA<<<512, 256, smemA>>>(u, v, m);
    k_trans<<<dim3(64, 64), 256>>>();
    k_rows<<<4096, 64>>>(gcl_b, dense_w, dense_b);
    k_q<<<20, 256>>>(P, a);
    k_gu<<<2048, 160>>>();
    k_final<<<dim3(64, 64), 256>>>(out);
    k_finalize<<<1, 256>>>(out, out_size);
}

// round 2
// speedup vs baseline: 1.0316x; 1.0316x over previous
#include <cuda_runtime.h>
#include <cstdint>
#include <cstddef>

#define NUK 2048
#define NVK 2048
#define RNC 5
#define DIMK 128
#define H0K 64
#define H1K 32
#define NUSERS 6040
#define NITEMS 3706
#define ROWP 3712

typedef unsigned long long ull;

// ---------------- scratch (static device memory; no allocations) ----------------
__device__ float d_sup[RNC * 4096 * H0K];       // sup[r][n][h]
__device__ float d_du[NVK];
__device__ float d_di[NUK];
__device__ unsigned char d_code[(size_t)NUK * NVK];
__device__ unsigned char d_codeT[(size_t)NVK * NUK];
__device__ float d_hidden[4096 * H1K];
__device__ float d_Q[RNC * H1K * H1K];
__device__ float d_gu[(size_t)NUK * 192];       // gu[u][e][6] (r padded to 6)
__device__ float d_acc2[2];

// FMA-pipe exp (avoids MUFU.EX2)
__device__ __forceinline__ float fexp(float x) {
    float y = x * 1.4426950408889634f;
    float t = y + 12582912.0f;
    int   ni = __float_as_int(t) - 0x4B400000;
    float n = t - 12582912.0f;
    float f = y - n;
    float p = 1.3333558e-3f;
    p = fmaf(p, f, 9.6181291e-3f);
    p = fmaf(p, f, 5.5504109e-2f);
    p = fmaf(p, f, 2.4022651e-1f);
    p = fmaf(p, f, 6.9314718e-1f);
    p = fmaf(p, f, 1.0f);
    return p * __int_as_float((ni + 127) << 23);
}

__device__ __forceinline__ ull pk2(float a, float b) {
    ull r; asm("mov.b64 %0,{%1,%2};" : "=l"(r) : "f"(a), "f"(b)); return r;
}
__device__ __forceinline__ ull fma2(ull a, ull b, ull c) {
    ull d; asm("fma.rn.f32x2 %0,%1,%2,%3;" : "=l"(d) : "l"(a), "l"(b), "l"(c)); return d;
}
__device__ __forceinline__ void upk2(ull v, float& lo, float& hi) {
    asm("mov.b64 {%0,%1},%2;" : "=f"(lo), "=f"(hi) : "l"(v));
}

// ---------------- k_sup (+ folded init & Q): register-blocked packed GEMM ----------------
#define SUPB 16
__global__ void __launch_bounds__(128) k_sup(const int* __restrict__ u, const int* __restrict__ v,
                      const float* __restrict__ ue, const float* __restrict__ ve,
                      const float* __restrict__ w,
                      const float* __restrict__ P, const float* __restrict__ a) {
    int tid = threadIdx.x;
    if (blockIdx.x >= 256) {
        // auxiliary block: zero accumulators + compute Q
        for (int i = tid; i < NVK; i += 128) d_du[i] = 0.f;
        if (tid < 2) d_acc2[tid] = 0.f;
        for (int idx = tid; idx < RNC * H1K * H1K; idx += 128) {
            int r = idx / (H1K * H1K); int de = idx % (H1K * H1K);
            d_Q[idx] = a[2 * r] * P[de] + a[2 * r + 1] * P[H1K * H1K + de];
        }
        return;
    }
    __shared__ float xs[SUPB][DIMK];
    int n0 = blockIdx.x * SUPB;
    for (int idx = tid; idx < SUPB * DIMK; idx += 128) {
        int nl = idx >> 7, d = idx & 127;
        int n = n0 + nl;
        const float* src = (n < NUK) ? (ue + (size_t)u[n] * DIMK)
                                     : (ve + (size_t)v[n - NUK] * DIMK);
        xs[nl][d] = src[d];
    }
    __syncthreads();
    int h2 = tid & 31, g = tid >> 5;
    int nb = g * 4;
    ull acc[4][5];
    #pragma unroll
    for (int i = 0; i < 4; i++)
        #pragma unroll
        for (int r = 0; r < 5; r++) acc[i][r] = 0ull;
    const float* wp_ = w + 2 * h2;
    #pragma unroll 4
    for (int d = 0; d < DIMK; d++) {
        ull xp0 = pk2(xs[nb][d], xs[nb][d]);
        ull xp1 = pk2(xs[nb + 1][d], xs[nb + 1][d]);
        ull xp2 = pk2(xs[nb + 2][d], xs[nb + 2][d]);
        ull xp3 = pk2(xs[nb + 3][d], xs[nb + 3][d]);
        #pragma unroll
        for (int r = 0; r < 5; r++) {
            ull wv = *(const ull*)(wp_ + (size_t)(r * DIMK + d) * H0K);
            acc[0][r] = fma2(wv, xp0, acc[0][r]);
            acc[1][r] = fma2(wv, xp1, acc[1][r]);
            acc[2][r] = fma2(wv, xp2, acc[2][r]);
            acc[3][r] = fma2(wv, xp3, acc[3][r]);
        }
    }
    #pragma unroll
    for (int i = 0; i < 4; i++)
        #pragma unroll
        for (int r = 0; r < 5; r++)
            *(ull*)&d_sup[((size_t)r * 4096 + n0 + nb + i) * H0K + 2 * h2] = acc[i][r];
}

// ---------------- pass A: read m rows once (float2); emit code, du, di ----------------
__global__ void k_passA(const int* __restrict__ u, const int* __restrict__ v,
                        const float* __restrict__ m) {
    extern __shared__ char smemraw[];
    int*   sv   = (int*)smemraw;
    float* rows = (float*)(smemraw + NVK * sizeof(int));
    __shared__ float wred[8];
    int tid = threadIdx.x;
    for (int idx = tid; idx < NVK; idx += 256) sv[idx] = v[idx];

    float du_loc[8];
    #pragma unroll
    for (int k = 0; k < 8; k++) du_loc[k] = 0.f;

    for (int ii = 0; ii < 4; ii++) {
        int i = blockIdx.x * 4 + ii;
        int Ui = u[i];
        __syncthreads();
        #pragma unroll
        for (int r = 0; r < RNC; r++) {
            const float2* src2 = (const float2*)(m + ((size_t)r * NUSERS + Ui) * NITEMS);
            float2* dst2 = (float2*)(rows + r * ROWP);
            for (int c2 = tid; c2 < NITEMS / 2; c2 += 256) dst2[c2] = src2[c2];
        }
        __syncthreads();
        float rowsum = 0.f;
        #pragma unroll
        for (int k = 0; k < 8; k++) {
            int j = tid + k * 256;
            int vj = sv[j];
            float vs = 0.f; int cls = 255;
            #pragma unroll
            for (int r = 0; r < RNC; r++) {
                float mv = rows[r * ROWP + vj];
                vs += mv;
                if (mv > 0.5f) cls = r;
            }
            du_loc[k] += vs; rowsum += vs;
            d_code[(size_t)i * NVK + j] = (unsigned char)cls;
        }
        #pragma unroll
        for (int o = 16; o > 0; o >>= 1) rowsum += __shfl_down_sync(0xffffffffu, rowsum, o);
        if ((tid & 31) == 0) wred[tid >> 5] = rowsum;
        __syncthreads();
        if (tid == 0) {
            float t2 = 0.f;
            #pragma unroll
            for (int wq = 0; wq < 8; wq++) t2 += wred[wq];
            d_di[i] = t2;
        }
    }
    #pragma unroll
    for (int k = 0; k < 8; k++) atomicAdd(&d_du[tid + k * 256], du_loc[k]);
}

// ---------------- transpose code -> codeT (uchar4-vectorized 32x32 tiles) ----------------
__global__ void k_trans() {
    __shared__ unsigned char t[32][36];
    int tid = threadIdx.x;
    int row = tid >> 3, c4 = (tid & 7) * 4;
    size_t bx = (size_t)blockIdx.x * 32, by = (size_t)blockIdx.y * 32;
    uchar4 val = *(const uchar4*)(d_code + (by + row) * NVK + bx + c4);
    t[c4][row] = val.x; t[c4 + 1][row] = val.y; t[c4 + 2][row] = val.z; t[c4 + 3][row] = val.w;
    __syncthreads();
    uchar4 o;
    o.x = t[row][c4]; o.y = t[row][c4 + 1]; o.z = t[row][c4 + 2]; o.w = t[row][c4 + 3];
    *(uchar4*)(d_codeT + (bx + row) * NUK + by + c4) = o;
}

// ---------------- rows: sparse scatter-sum, z->relu->dense->sigmoid ----------------
__global__ void k_rows(const float* __restrict__ gclb, const float* __restrict__ dw,
                       const float* __restrict__ db) {
    int n = blockIdx.x;
    int h = threadIdx.x;  // 64
    __shared__ unsigned char crow[2048];
    __shared__ unsigned short lst[2048];
    __shared__ int scnt;
    __shared__ float zs[H0K];

    const unsigned char* src; int off; float deg;
    if (n < NUK) { src = d_code  + (size_t)n * NVK;        off = NUK; deg = d_du[n]; }
    else         { src = d_codeT + (size_t)(n - NUK) * NUK; off = 0;   deg = d_di[n - NUK]; }
    if (h == 0) scnt = 0;
    for (int idx = h; idx < 2048 / 16; idx += 64)
        ((uint4*)crow)[idx] = ((const uint4*)src)[idx];
    __syncthreads();
    #pragma unroll 4
    for (int b = 0; b < 32; b++) {
        int jj = h * 32 + b;
        unsigned char c = crow[jj];
        if (c < RNC) { int p = atomicAdd(&scnt, 1); lst[p] = (unsigned short)((jj << 3) | c); }
    }
    __syncthreads();
    int cnt = scnt;
    float a0 = 0.f, a1 = 0.f, a2 = 0.f, a3 = 0.f;
    int k = 0;
    for (; k + 4 <= cnt; k += 4) {
        unsigned short e0 = lst[k], e1 = lst[k + 1], e2 = lst[k + 2], e3 = lst[k + 3];
        a0 += d_sup[(((e0 & 7) * 4096) + off + (e0 >> 3)) * H0K + h];
        a1 += d_sup[(((e1 & 7) * 4096) + off + (e1 >> 3)) * H0K + h];
        a2 += d_sup[(((e2 & 7) * 4096) + off + (e2 >> 3)) * H0K + h];
        a3 += d_sup[(((e3 & 7) * 4096) + off + (e3 >> 3)) * H0K + h];
    }
    for (; k < cnt; k++) {
        unsigned short e0 = lst[k];
        a0 += d_sup[(((e0 & 7) * 4096) + off + (e0 >> 3)) * H0K + h];
    }
    float acc = (a0 + a1) + (a2 + a3);
    float ad = fabsf(deg);
    float cinv = (ad > 0.f) ? (1.f / ad) : 0.f;
    float z = fmaf(acc, cinv, 5.f * gclb[h]);
    zs[h] = fmaxf(z, 0.f);
    __syncthreads();
    if (h < H1K) {
        float s = db[h];
        #pragma unroll
        for (int h0 = 0; h0 < H0K; h0++) s = fmaf(zs[h0], dw[h0 * H1K + h], s);
        d_hidden[n * H1K + h] = 1.f / (1.f + fexp(-s));
    }
}

// ---------------- gu[u][e][rr] = sum_d hu[u][d] Q[rr][d][e] (rr padded to 6) ----------------
__global__ void k_gu() {
    int n = blockIdx.x;
    __shared__ float hs[H1K];
    int t = threadIdx.x;  // 192
    if (t < H1K) hs[t] = d_hidden[n * H1K + t];
    __syncthreads();
    int e = t / 6, rr = t % 6;
    float acc = 0.f;
    if (rr < RNC) {
        #pragma unroll
        for (int d = 0; d < H1K; d++) acc = fmaf(hs[d], d_Q[(rr * H1K + d) * H1K + e], acc);
    }
    d_gu[(size_t)n * 192 + e * 6 + rr] = acc;
}

// ---------------- final fused: packed-f32x2 logits + softmax + m_hat + loss + rmse ----------------
__global__ void __launch_bounds__(256) k_final(float* __restrict__ out) {
    __shared__ float sgu[32 * 192];       // [u][e][6]
    __shared__ float shv[32 * 33];
    __shared__ unsigned char scd[1024];
    __shared__ float red[16];
    int tid = threadIdx.x;
    int ub = blockIdx.y * 32, vb = blockIdx.x * 32;

    for (int idx = tid; idx < 6144; idx += 256) sgu[idx] = d_gu[(size_t)ub * 192 + idx];
    for (int idx = tid; idx < 1024; idx += 256)
        shv[(idx >> 5) * 33 + (idx & 31)] = d_hidden[(size_t)(NUK + vb + (idx >> 5)) * H1K + (idx & 31)];
    {
        int row = tid >> 3, c4 = (tid & 7) * 4;
        *(uchar4*)(scd + row * 32 + c4) = *(const uchar4*)(d_code + (size_t)(ub + row) * NVK + vb + c4);
    }
    __syncthreads();

    int u0 = (tid >> 4) * 2, v0 = (tid & 15) * 2;
    float hva[32], hvb[32];
    #pragma unroll
    for (int e = 0; e < 32; e++) { hva[e] = shv[v0 * 33 + e]; hvb[e] = shv[(v0 + 1) * 33 + e]; }

    ull acc[12];   // [p(3 r-pairs)][s(4: u0va,u0vb,u1va,u1vb)]
    #pragma unroll
    for (int q = 0; q < 12; q++) acc[q] = 0ull;
    const float* g0b = sgu + u0 * 192;
    const float* g1b = g0b + 192;
    #pragma unroll
    for (int e = 0; e < 32; e++) {
        ull ga0 = *(const ull*)(g0b + e * 6);
        ull ga1 = *(const ull*)(g0b + e * 6 + 2);
        ull ga2 = *(const ull*)(g0b + e * 6 + 4);
        ull gb0 = *(const ull*)(g1b + e * 6);
        ull gb1 = *(const ull*)(g1b + e * 6 + 2);
        ull gb2 = *(const ull*)(g1b + e * 6 + 4);
        ull hap = pk2(hva[e], hva[e]);
        ull hbp = pk2(hvb[e], hvb[e]);
        acc[0]  = fma2(ga0, hap, acc[0]);  acc[1]  = fma2(ga0, hbp, acc[1]);
        acc[2]  = fma2(gb0, hap, acc[2]);  acc[3]  = fma2(gb0, hbp, acc[3]);
        acc[4]  = fma2(ga1, hap, acc[4]);  acc[5]  = fma2(ga1, hbp, acc[5]);
        acc[6]  = fma2(gb1, hap, acc[6]);  acc[7]  = fma2(gb1, hbp, acc[7]);
        acc[8]  = fma2(ga2, hap, acc[8]);  acc[9]  = fma2(ga2, hbp, acc[9]);
        acc[10] = fma2(gb2, hap, acc[10]); acc[11] = fma2(gb2, hbp, acc[11]);
    }
    // unpack: L[r][s]
    float L[5][4]; float dummy;
    #pragma unroll
    for (int s = 0; s < 4; s++) {
        upk2(acc[s],     L[0][s], L[1][s]);
        upk2(acc[4 + s], L[2][s], L[3][s]);
        upk2(acc[8 + s], L[4][s], dummy);
    }

    float loss_t = 0.f, rmse_t = 0.f;
    float mh[4];
    #pragma unroll
    for (int p = 0; p < 4; p++) {
        float l0 = L[0][p], l1 = L[1][p], l2 = L[2][p], l3 = L[3][p], l4 = L[4][p];
        float mx = fmaxf(fmaxf(fmaxf(l0, l1), fmaxf(l2, l3)), l4);
        float e0 = fexp(l0 - mx), e1 = fexp(l1 - mx), e2 = fexp(l2 - mx),
              e3 = fexp(l3 - mx), e4 = fexp(l4 - mx);
        float s = ((e0 + e1) + (e2 + e3)) + e4;
        float num = fmaf(2.f, e1, e0);
        num = fmaf(3.f, e2, num);
        num = fmaf(4.f, e3, num);
        num = fmaf(5.f, e4, num);
        float inv = 1.f / s;
        float m_hat = num * inv;
        mh[p] = m_hat;
        int du_ = p >> 1, dv_ = p & 1;   // p: s index = u-offset*2 + v-offset
        unsigned char c = scd[(u0 + du_) * 32 + (v0 + dv_)];
        if (c < 5) {
            float lc = l0;
            lc = (c == 1) ? l1 : lc; lc = (c == 2) ? l2 : lc;
            lc = (c == 3) ? l3 : lc; lc = (c == 4) ? l4 : lc;
            loss_t += (mx + __logf(s)) - lc;
            float dd = m_hat - (float)(c + 1);
            rmse_t = fmaf(dd, dd, rmse_t);
        }
    }
    {
        size_t base = (size_t)(ub + u0) * NVK + vb + v0;
        *(float2*)(out + base)       = make_float2(mh[0], mh[1]);
        *(float2*)(out + base + NVK) = make_float2(mh[2], mh[3]);
    }
    #pragma unroll
    for (int o = 16; o > 0; o >>= 1) {
        loss_t += __shfl_down_sync(0xffffffffu, loss_t, o);
        rmse_t += __shfl_down_sync(0xffffffffu, rmse_t, o);
    }
    int lane = tid & 31, w = tid >> 5;
    if (lane == 0) { red[w] = loss_t; red[8 + w] = rmse_t; }
    __syncthreads();
    if (tid == 0) {
        float ls = 0.f, rs = 0.f;
        #pragma unroll
        for (int q = 0; q < 8; q++) { ls += red[q]; rs += red[8 + q]; }
        atomicAdd(&d_acc2[0], ls);
        atomicAdd(&d_acc2[1], rs);
    }
}

// ---------------- finalize ----------------
__global__ void k_finalize(float* __restrict__ out, int out_size) {
    __shared__ float rd[256];
    float s = 0.f;
    for (int idx = threadIdx.x; idx < NVK; idx += 256) s += d_du[idx];
    rd[threadIdx.x] = s;
    __syncthreads();
    for (int o = 128; o > 0; o >>= 1) {
        if (threadIdx.x < o) rd[threadIdx.x] += rd[threadIdx.x + o];
        __syncthreads();
    }
    if (threadIdx.x == 0) {
        float cnt = fmaxf(rd[0], 1.f);
        out[out_size - 2] = d_acc2[0] / cnt;
        out[out_size - 1] = sqrtf(d_acc2[1] / cnt);
    }
}

extern "C" void kernel_launch(void* const* d_in, const int* in_sizes, int n_in,
                              void* d_out, int out_size) {
    const int*   u       = (const int*)d_in[0];
    const int*   v       = (const int*)d_in[1];
    const float* m       = (const float*)d_in[2];
    const float* u_emb   = (const float*)d_in[3];
    const float* v_emb   = (const float*)d_in[4];
    const float* gcl_w   = (const float*)d_in[5];
    const float* gcl_b   = (const float*)d_in[6];
    const float* dense_w = (const float*)d_in[7];
    const float* dense_b = (const float*)d_in[8];
    const float* P       = (const float*)d_in[9];
    const float* a       = (const float*)d_in[10];
    float* out = (float*)d_out;

    const size_t smemA = NVK * sizeof(int) + (size_t)RNC * ROWP * sizeof(float);
    cudaFuncSetAttribute(k_passA, cudaFuncAttributeMaxDynamicSharedMemorySize, (int)smemA);

    k_sup<<<257, 128>>>(u, v, u_emb, v_emb, gcl_w, P, a);
    k_passA<<<512, 256, smemA>>>(u, v, m);
    k_trans<<<dim3(64, 64), 256>>>();
    k_rows<<<4096, 64>>>(gcl_b, dense_w, dense_b);
    k_gu<<<2048, 192>>>();
    k_final<<<dim3(64, 64), 256>>>(out);
    k_finalize<<<1, 256>>>(out, out_size);
}

// round 3
// speedup vs baseline: 1.5252x; 1.4785x over previous
#include <cuda_runtime.h>
#include <cstdint>
#include <cstddef>

#define NUK 2048
#define NVK 2048
#define RNC 5
#define DIMK 128
#define H0K 64
#define H1K 32
#define NUSERS 6040
#define NITEMS 3706
#define ROWP 3712

typedef unsigned long long ull;

// ---------------- scratch ----------------
__device__ float d_sup[RNC * 4096 * H0K];
__device__ float d_du[NVK];
__device__ float d_di[NUK];
__device__ unsigned char d_code[(size_t)NUK * NVK];
__device__ unsigned char d_codeT[(size_t)NVK * NUK];
__device__ float d_hidden[4096 * H1K];
__device__ float d_t[(size_t)NUK * 64];   // t[u][e][b]  (b-pairs packed)
__device__ float d_acc2[2];

// FMA-pipe exp
__device__ __forceinline__ float fexp(float x) {
    float y = x * 1.4426950408889634f;
    float t = y + 12582912.0f;
    int   ni = __float_as_int(t) - 0x4B400000;
    float n = t - 12582912.0f;
    float f = y - n;
    float p = 1.3333558e-3f;
    p = fmaf(p, f, 9.6181291e-3f);
    p = fmaf(p, f, 5.5504109e-2f);
    p = fmaf(p, f, 2.4022651e-1f);
    p = fmaf(p, f, 6.9314718e-1f);
    p = fmaf(p, f, 1.0f);
    return p * __int_as_float((ni + 127) << 23);
}
__device__ __forceinline__ ull pk2(float a, float b) {
    ull r; asm("mov.b64 %0,{%1,%2};" : "=l"(r) : "f"(a), "f"(b)); return r;
}
__device__ __forceinline__ ull fma2(ull a, ull b, ull c) {
    ull d; asm("fma.rn.f32x2 %0,%1,%2,%3;" : "=l"(d) : "l"(a), "l"(b), "l"(c)); return d;
}
__device__ __forceinline__ void upk2(ull v, float& lo, float& hi) {
    asm("mov.b64 {%0,%1},%2;" : "=f"(lo), "=f"(hi) : "l"(v));
}
__device__ __forceinline__ uint32_t s2u(const void* p) {
    uint32_t a;
    asm("{.reg .u64 t; cvta.to.shared.u64 t, %1; cvt.u32.u64 %0, t;}" : "=r"(a) : "l"(p));
    return a;
}

// ---------------- k_sup: packed register-blocked GEMM (+ zeroing aux block) ----------------
#define SUPB 16
__global__ void __launch_bounds__(128) k_sup(const int* __restrict__ u, const int* __restrict__ v,
                      const float* __restrict__ ue, const float* __restrict__ ve,
                      const float* __restrict__ w) {
    int tid = threadIdx.x;
    if (blockIdx.x >= 256) {
        for (int i = tid; i < NVK; i += 128) { d_du[i] = 0.f; d_di[i] = 0.f; }
        if (tid < 2) d_acc2[tid] = 0.f;
        return;
    }
    __shared__ float xs[SUPB][DIMK];
    int n0 = blockIdx.x * SUPB;
    for (int idx = tid; idx < SUPB * DIMK; idx += 128) {
        int nl = idx >> 7, d = idx & 127;
        int n = n0 + nl;
        const float* src = (n < NUK) ? (ue + (size_t)u[n] * DIMK)
                                     : (ve + (size_t)v[n - NUK] * DIMK);
        xs[nl][d] = src[d];
    }
    __syncthreads();
    int h2 = tid & 31, g = tid >> 5;
    int nb = g * 4;
    ull acc[4][5];
    #pragma unroll
    for (int i = 0; i < 4; i++)
        #pragma unroll
        for (int r = 0; r < 5; r++) acc[i][r] = 0ull;
    const float* wp_ = w + 2 * h2;
    #pragma unroll 4
    for (int d = 0; d < DIMK; d++) {
        ull xp0 = pk2(xs[nb][d], xs[nb][d]);
        ull xp1 = pk2(xs[nb + 1][d], xs[nb + 1][d]);
        ull xp2 = pk2(xs[nb + 2][d], xs[nb + 2][d]);
        ull xp3 = pk2(xs[nb + 3][d], xs[nb + 3][d]);
        #pragma unroll
        for (int r = 0; r < 5; r++) {
            ull wv = *(const ull*)(wp_ + (size_t)(r * DIMK + d) * H0K);
            acc[0][r] = fma2(wv, xp0, acc[0][r]);
            acc[1][r] = fma2(wv, xp1, acc[1][r]);
            acc[2][r] = fma2(wv, xp2, acc[2][r]);
            acc[3][r] = fma2(wv, xp3, acc[3][r]);
        }
    }
    #pragma unroll
    for (int i = 0; i < 4; i++)
        #pragma unroll
        for (int r = 0; r < 5; r++)
            *(ull*)&d_sup[((size_t)r * 4096 + n0 + nb + i) * H0K + 2 * h2] = acc[i][r];
}

// ---------------- pass A: stream 5 m-rows per u via cp.async; emit code only ----------------
__global__ void __launch_bounds__(256) k_passA(const int* __restrict__ u, const int* __restrict__ v,
                                               const float* __restrict__ m) {
    extern __shared__ float rows[];   // 5 * ROWP floats
    int tid = threadIdx.x;
    int i = blockIdx.x;
    int Ui = u[i];
    int vj[8];
    #pragma unroll
    for (int k = 0; k < 8; k++) vj[k] = v[tid + k * 256];

    uint32_t sbase = s2u(rows);
    #pragma unroll
    for (int r = 0; r < RNC; r++) {
        const float* src = m + ((size_t)r * NUSERS + Ui) * NITEMS;
        uint32_t dst = sbase + r * ROWP * 4;
        // 3706 floats = 1853 x 8B chunks (8B-aligned always)
        for (int c = tid; c < 1853; c += 256)
            asm volatile("cp.async.ca.shared.global [%0], [%1], 8;"
                         :: "r"(dst + c * 8), "l"(src + c * 2));
    }
    asm volatile("cp.async.commit_group;");
    asm volatile("cp.async.wait_group 0;");
    __syncthreads();

    #pragma unroll
    for (int k = 0; k < 8; k++) {
        int j = tid + k * 256;
        int cls = 255;
        #pragma unroll
        for (int r = 0; r < RNC; r++)
            if (rows[r * ROWP + vj[k]] > 0.5f) cls = r;
        d_code[(size_t)i * NVK + j] = (unsigned char)cls;
    }
}

// ---------------- transpose + degree counts ----------------
__global__ void k_trans() {
    __shared__ unsigned char t[32][36];
    int tid = threadIdx.x;
    int row = tid >> 3, c4 = (tid & 7) * 4;
    size_t bx = (size_t)blockIdx.x * 32, by = (size_t)blockIdx.y * 32;
    uchar4 val = *(const uchar4*)(d_code + (by + row) * NVK + bx + c4);
    int dic = (val.x < 5) + (val.y < 5) + (val.z < 5) + (val.w < 5);
    t[c4][row] = val.x; t[c4 + 1][row] = val.y; t[c4 + 2][row] = val.z; t[c4 + 3][row] = val.w;
    dic += __shfl_down_sync(0xffffffffu, dic, 4, 8);
    dic += __shfl_down_sync(0xffffffffu, dic, 2, 8);
    dic += __shfl_down_sync(0xffffffffu, dic, 1, 8);
    if ((tid & 7) == 0 && dic) atomicAdd(&d_di[by + row], (float)dic);
    __syncthreads();
    uchar4 o;
    o.x = t[row][c4]; o.y = t[row][c4 + 1]; o.z = t[row][c4 + 2]; o.w = t[row][c4 + 3];
    *(uchar4*)(d_codeT + (bx + row) * NUK + by + c4) = o;
    int duc = (o.x < 5) + (o.y < 5) + (o.z < 5) + (o.w < 5);
    duc += __shfl_down_sync(0xffffffffu, duc, 4, 8);
    duc += __shfl_down_sync(0xffffffffu, duc, 2, 8);
    duc += __shfl_down_sync(0xffffffffu, duc, 1, 8);
    if ((tid & 7) == 0 && duc) atomicAdd(&d_du[bx + row], (float)duc);
}

// ---------------- rows: ballot list, f32x2 gather, dense, sigmoid, t = hu·P ----------------
__global__ void __launch_bounds__(64) k_rows(const float* __restrict__ gclb, const float* __restrict__ dw,
                                             const float* __restrict__ db, const float* __restrict__ P) {
    int n = blockIdx.x;
    int tid = threadIdx.x, lane = tid & 31, w = tid >> 5;
    __shared__ unsigned char crow[2048];
    __shared__ unsigned short lst[2][1024];
    __shared__ ull accs[32];
    __shared__ float zs[H0K];
    __shared__ float hid[H1K];

    const unsigned char* src; int off; float deg;
    if (n < NUK) { src = d_code  + (size_t)n * NVK;        off = NUK; deg = d_du[n]; }
    else         { src = d_codeT + (size_t)(n - NUK) * NUK; off = 0;   deg = d_di[n - NUK]; }
    for (int idx = tid; idx < 128; idx += 64)
        ((uint4*)crow)[idx] = ((const uint4*)src)[idx];
    __syncthreads();

    // ballot-compaction: warp w covers j in [w*1024, w*1024+1024)
    int cnt = 0;
    unsigned short* mylst = lst[w];
    #pragma unroll 4
    for (int rd = 0; rd < 32; rd++) {
        int j = w * 1024 + rd * 32 + lane;
        unsigned char c = crow[j];
        bool act = c < RNC;
        unsigned mask = __ballot_sync(0xffffffffu, act);
        if (act) mylst[cnt + __popc(mask & ((1u << lane) - 1))] = (unsigned short)((j << 3) | c);
        cnt += __popc(mask);
    }

    // gather: each warp its own list; lane owns columns (2*lane, 2*lane+1)
    ull one2 = pk2(1.f, 1.f);
    ull a8[8];
    #pragma unroll
    for (int q = 0; q < 8; q++) a8[q] = 0ull;
    int k = 0;
    for (; k + 8 <= cnt; k += 8) {
        #pragma unroll
        for (int q = 0; q < 8; q++) {
            unsigned short e = mylst[k + q];
            const ull* p = (const ull*)(d_sup + ((size_t)((e & 7) * 4096) + off + (e >> 3)) * H0K) + lane;
            a8[q] = fma2(*p, one2, a8[q]);
        }
    }
    for (; k < cnt; k++) {
        unsigned short e = mylst[k];
        const ull* p = (const ull*)(d_sup + ((size_t)((e & 7) * 4096) + off + (e >> 3)) * H0K) + lane;
        a8[0] = fma2(*p, one2, a8[0]);
    }
    ull acc = fma2(a8[0], one2, a8[1]);
    ull ac2 = fma2(a8[2], one2, a8[3]);
    ull ac3 = fma2(a8[4], one2, a8[5]);
    ull ac4 = fma2(a8[6], one2, a8[7]);
    acc = fma2(acc, one2, ac2);
    ac3 = fma2(ac3, one2, ac4);
    acc = fma2(acc, one2, ac3);

    if (w == 1) accs[lane] = acc;
    __syncthreads();
    if (w == 0) {
        acc = fma2(accs[lane], one2, acc);
        float f0, f1; upk2(acc, f0, f1);
        float ad = fabsf(deg);
        float cinv = (ad > 0.f) ? (1.f / ad) : 0.f;
        float z0 = fmaf(f0, cinv, 5.f * gclb[2 * lane]);
        float z1 = fmaf(f1, cinv, 5.f * gclb[2 * lane + 1]);
        zs[2 * lane]     = fmaxf(z0, 0.f);
        zs[2 * lane + 1] = fmaxf(z1, 0.f);
    }
    __syncthreads();
    if (tid < H1K) {
        float s = db[tid];
        #pragma unroll
        for (int h0 = 0; h0 < H0K; h0++) s = fmaf(zs[h0], dw[h0 * H1K + tid], s);
        float hv = 1.f / (1.f + fexp(-s));
        d_hidden[n * H1K + tid] = hv;
        hid[tid] = hv;
    }
    __syncthreads();
    if (n < NUK) {
        int b = tid >> 5, e = tid & 31;
        float t = 0.f;
        #pragma unroll
        for (int d = 0; d < H1K; d++) t = fmaf(hid[d], P[((size_t)b * H1K + d) * H1K + e], t);
        d_t[(size_t)n * 64 + e * 2 + b] = t;
    }
}

// ---------------- final fused: rank-2 logits + softmax + m_hat + loss + rmse ----------------
__global__ void __launch_bounds__(256) k_final(const float* __restrict__ aw, float* __restrict__ out) {
    __shared__ float st[32 * 64];      // [u][e*2+b]
    __shared__ float shv[32 * 33];
    __shared__ unsigned char scd[1024];
    __shared__ float red[16];
    int tid = threadIdx.x;
    int ub = blockIdx.y * 32, vb = blockIdx.x * 32;

    for (int idx = tid; idx < 2048; idx += 256) st[idx] = d_t[(size_t)ub * 64 + idx];
    for (int idx = tid; idx < 1024; idx += 256)
        shv[(idx >> 5) * 33 + (idx & 31)] = d_hidden[(size_t)(NUK + vb + (idx >> 5)) * H1K + (idx & 31)];
    {
        int row = tid >> 3, c4 = (tid & 7) * 4;
        *(uchar4*)(scd + row * 32 + c4) = *(const uchar4*)(d_code + (size_t)(ub + row) * NVK + vb + c4);
    }
    float ar[10];
    #pragma unroll
    for (int q = 0; q < 10; q++) ar[q] = aw[q];
    __syncthreads();

    int u0 = (tid >> 4) * 2, v0 = (tid & 15) * 2;
    float hva[32], hvb[32];
    #pragma unroll
    for (int e = 0; e < 32; e++) { hva[e] = shv[v0 * 33 + e]; hvb[e] = shv[(v0 + 1) * 33 + e]; }

    ull acc[4] = {0ull, 0ull, 0ull, 0ull};   // (s0,s1) for u0va,u0vb,u1va,u1vb
    const float* t0 = st + u0 * 64;
    const float* t1 = t0 + 64;
    #pragma unroll
    for (int e = 0; e < 32; e++) {
        ull ta = *(const ull*)(t0 + e * 2);
        ull tb = *(const ull*)(t1 + e * 2);
        ull hap = pk2(hva[e], hva[e]);
        ull hbp = pk2(hvb[e], hvb[e]);
        acc[0] = fma2(ta, hap, acc[0]);
        acc[1] = fma2(ta, hbp, acc[1]);
        acc[2] = fma2(tb, hap, acc[2]);
        acc[3] = fma2(tb, hbp, acc[3]);
    }

    float loss_t = 0.f, rmse_t = 0.f;
    float mh[4];
    #pragma unroll
    for (int p = 0; p < 4; p++) {
        float s0, s1; upk2(acc[p], s0, s1);
        float l0 = fmaf(ar[0], s0, ar[1] * s1);
        float l1 = fmaf(ar[2], s0, ar[3] * s1);
        float l2 = fmaf(ar[4], s0, ar[5] * s1);
        float l3 = fmaf(ar[6], s0, ar[7] * s1);
        float l4 = fmaf(ar[8], s0, ar[9] * s1);
        float mx = fmaxf(fmaxf(fmaxf(l0, l1), fmaxf(l2, l3)), l4);
        float e0 = fexp(l0 - mx), e1 = fexp(l1 - mx), e2 = fexp(l2 - mx),
              e3 = fexp(l3 - mx), e4 = fexp(l4 - mx);
        float s = ((e0 + e1) + (e2 + e3)) + e4;
        float num = fmaf(2.f, e1, e0);
        num = fmaf(3.f, e2, num);
        num = fmaf(4.f, e3, num);
        num = fmaf(5.f, e4, num);
        float inv = 1.f / s;
        float m_hat = num * inv;
        mh[p] = m_hat;
        int du_ = p >> 1, dv_ = p & 1;
        unsigned char c = scd[(u0 + du_) * 32 + (v0 + dv_)];
        if (c < 5) {
            float lc = l0;
            lc = (c == 1) ? l1 : lc; lc = (c == 2) ? l2 : lc;
            lc = (c == 3) ? l3 : lc; lc = (c == 4) ? l4 : lc;
            loss_t += (mx + __logf(s)) - lc;
            float dd = m_hat - (float)(c + 1);
            rmse_t = fmaf(dd, dd, rmse_t);
        }
    }
    {
        size_t base = (size_t)(ub + u0) * NVK + vb + v0;
        *(float2*)(out + base)       = make_float2(mh[0], mh[1]);
        *(float2*)(out + base + NVK) = make_float2(mh[2], mh[3]);
    }
    #pragma unroll
    for (int o = 16; o > 0; o >>= 1) {
        loss_t += __shfl_down_sync(0xffffffffu, loss_t, o);
        rmse_t += __shfl_down_sync(0xffffffffu, rmse_t, o);
    }
    int lane = tid & 31, w = tid >> 5;
    if (lane == 0) { red[w] = loss_t; red[8 + w] = rmse_t; }
    __syncthreads();
    if (tid == 0) {
        float ls = 0.f, rs = 0.f;
        #pragma unroll
        for (int q = 0; q < 8; q++) { ls += red[q]; rs += red[8 + q]; }
        atomicAdd(&d_acc2[0], ls);
        atomicAdd(&d_acc2[1], rs);
    }
}

// ---------------- finalize ----------------
__global__ void k_finalize(float* __restrict__ out, int out_size) {
    __shared__ float rd[256];
    float s = 0.f;
    for (int idx = threadIdx.x; idx < NVK; idx += 256) s += d_du[idx];
    rd[threadIdx.x] = s;
    __syncthreads();
    for (int o = 128; o > 0; o >>= 1) {
        if (threadIdx.x < o) rd[threadIdx.x] += rd[threadIdx.x + o];
        __syncthreads();
    }
    if (threadIdx.x == 0) {
        float cnt = fmaxf(rd[0], 1.f);
        out[out_size - 2] = d_acc2[0] / cnt;
        out[out_size - 1] = sqrtf(d_acc2[1] / cnt);
    }
}

extern "C" void kernel_launch(void* const* d_in, const int* in_sizes, int n_in,
                              void* d_out, int out_size) {
    const int*   u       = (const int*)d_in[0];
    const int*   v       = (const int*)d_in[1];
    const float* m       = (const float*)d_in[2];
    const float* u_emb   = (const float*)d_in[3];
    const float* v_emb   = (const float*)d_in[4];
    const float* gcl_w   = (const float*)d_in[5];
    const float* gcl_b   = (const float*)d_in[6];
    const float* dense_w = (const float*)d_in[7];
    const float* dense_b = (const float*)d_in[8];
    const float* P       = (const float*)d_in[9];
    const float* a       = (const float*)d_in[10];
    float* out = (float*)d_out;

    const int smemA = RNC * ROWP * sizeof(float);   // 74240
    cudaFuncSetAttribute(k_passA, cudaFuncAttributeMaxDynamicSharedMemorySize, smemA);

    k_sup<<<257, 128>>>(u, v, u_emb, v_emb, gcl_w);
    k_passA<<<2048, 256, smemA>>>(u, v, m);
    k_trans<<<dim3(64, 64), 256>>>();
    k_rows<<<4096, 64>>>(gcl_b, dense_w, dense_b, P);
    k_final<<<dim3(64, 64), 256>>>(a, out);
    k_finalize<<<1, 256>>>(out, out_size);
}

// round 4
// speedup vs baseline: 1.6314x; 1.0696x over previous
#include <cuda_runtime.h>
#include <cstdint>
#include <cstddef>

#define NUK 2048
#define NVK 2048
#define RNC 5
#define DIMK 128
#define H0K 64
#define H1K 32
#define NUSERS 6040
#define NITEMS 3706
#define ROWP 3712
#define CAP 512

typedef unsigned long long ull;

// ---------------- scratch ----------------
__device__ float d_sup[RNC * 4096 * H0K];
__device__ unsigned char d_code[(size_t)NUK * NVK];
__device__ int d_cntU[NUK];                 // edges per u-row  (= di)
__device__ int d_cntV[NVK];                 // edges per v-row  (= du)
__device__ unsigned d_elistU[(size_t)NUK * CAP];
__device__ unsigned d_elistV[(size_t)NVK * CAP];
__device__ float d_hidden[4096 * H1K];
__device__ float d_t[(size_t)NUK * 64];     // t[u][e*2+b]
__device__ float d_b8[8];                   // shifted a-coeffs
__device__ float d_acc2[2];
__device__ unsigned d_ticket;

// FMA-pipe exp (scalar, for sigmoid)
__device__ __forceinline__ float fexp(float x) {
    float y = x * 1.4426950408889634f;
    float t = y + 12582912.0f;
    int   ni = __float_as_int(t) - 0x4B400000;
    float n = t - 12582912.0f;
    float f = y - n;
    float p = 1.3333558e-3f;
    p = fmaf(p, f, 9.6181291e-3f);
    p = fmaf(p, f, 5.5504109e-2f);
    p = fmaf(p, f, 2.4022651e-1f);
    p = fmaf(p, f, 6.9314718e-1f);
    p = fmaf(p, f, 1.0f);
    return p * __int_as_float((ni + 127) << 23);
}
__device__ __forceinline__ ull pk2(float a, float b) {
    ull r; asm("mov.b64 %0,{%1,%2};" : "=l"(r) : "f"(a), "f"(b)); return r;
}
__device__ __forceinline__ ull fma2(ull a, ull b, ull c) {
    ull d; asm("fma.rn.f32x2 %0,%1,%2,%3;" : "=l"(d) : "l"(a), "l"(b), "l"(c)); return d;
}
__device__ __forceinline__ ull mul2(ull a, ull b) {
    ull d; asm("mul.rn.f32x2 %0,%1,%2;" : "=l"(d) : "l"(a), "l"(b)); return d;
}
__device__ __forceinline__ ull add2(ull a, ull b) {
    ull d; asm("add.rn.f32x2 %0,%1,%2;" : "=l"(d) : "l"(a), "l"(b)); return d;
}
__device__ __forceinline__ ull sub2(ull a, ull b) {
    ull d; asm("sub.rn.f32x2 %0,%1,%2;" : "=l"(d) : "l"(a), "l"(b)); return d;
}
__device__ __forceinline__ void upk2(ull v, float& lo, float& hi) {
    asm("mov.b64 {%0,%1},%2;" : "=f"(lo), "=f"(hi) : "l"(v));
}
__device__ __forceinline__ uint32_t s2u(const void* p) {
    uint32_t a;
    asm("{.reg .u64 t; cvta.to.shared.u64 t, %1; cvt.u32.u64 %0, t;}" : "=r"(a) : "l"(p));
    return a;
}

// packed 2-wide exp: e^{lo}, e^{hi}
__device__ __forceinline__ ull fexp2(ull l2) {
    const ull LG2   = 0x3FB8AA3B3FB8AA3Bull;   // (log2e, log2e)
    const ull MAGIC = 0x4B4000004B400000ull;   // (12582912, 12582912)
    ull t2 = fma2(l2, LG2, MAGIC);
    ull nn = sub2(MAGIC, t2);                  // -n
    ull f2 = fma2(l2, LG2, nn);                // f = y - n
    const ull C0 = 0x3AAEC96F3AAEC96Full;      // 1.3333558e-3
    const ull C1 = 0x3C1D94FC3C1D94FCull;      // 9.6181291e-3
    const ull C2 = 0x3D6357CF3D6357CFull;      // 5.5504109e-2
    const ull C3 = 0x3E75FDF03E75FDF0ull;      // 2.4022651e-1
    const ull C4 = 0x3F3172183F317218ull;      // 6.9314718e-1
    const ull C5 = 0x3F8000003F800000ull;      // 1.0
    ull p = fma2(C0, f2, C1);
    p = fma2(p, f2, C2);
    p = fma2(p, f2, C3);
    p = fma2(p, f2, C4);
    p = fma2(p, f2, C5);
    unsigned tlo = (unsigned)t2, thi = (unsigned)(t2 >> 32);
    const unsigned CC = (unsigned)(127 - 0x4B400000);
    unsigned slo = (tlo + CC) << 23;
    unsigned shi = (thi + CC) << 23;
    ull sc = ((ull)shi << 32) | slo;
    return mul2(p, sc);
}

// ---------------- k_sup: packed register-blocked GEMM (+ aux init block) ----------------
#define SUPB 16
__global__ void __launch_bounds__(128) k_sup(const int* __restrict__ u, const int* __restrict__ v,
                      const float* __restrict__ ue, const float* __restrict__ ve,
                      const float* __restrict__ w, const float* __restrict__ a) {
    int tid = threadIdx.x;
    if (blockIdx.x >= 256) {
        for (int i = tid; i < NUK; i += 128) { d_cntU[i] = 0; d_cntV[i] = 0; }
        if (tid < 2) d_acc2[tid] = 0.f;
        if (tid == 2) d_ticket = 0u;
        if (tid == 0) {
            float a00 = a[0], a01 = a[1];
            d_b8[0] = a[2] - a00; d_b8[1] = a[4] - a00;
            d_b8[2] = a[3] - a01; d_b8[3] = a[5] - a01;
            d_b8[4] = a[6] - a00; d_b8[5] = a[8] - a00;
            d_b8[6] = a[7] - a01; d_b8[7] = a[9] - a01;
        }
        return;
    }
    __shared__ float xs[SUPB][DIMK];
    int n0 = blockIdx.x * SUPB;
    for (int idx = tid; idx < SUPB * DIMK; idx += 128) {
        int nl = idx >> 7, d = idx & 127;
        int n = n0 + nl;
        const float* src = (n < NUK) ? (ue + (size_t)u[n] * DIMK)
                                     : (ve + (size_t)v[n - NUK] * DIMK);
        xs[nl][d] = src[d];
    }
    __syncthreads();
    int h2 = tid & 31, g = tid >> 5;
    int nb = g * 4;
    ull acc[4][5];
    #pragma unroll
    for (int i = 0; i < 4; i++)
        #pragma unroll
        for (int r = 0; r < 5; r++) acc[i][r] = 0ull;
    const float* wp_ = w + 2 * h2;
    #pragma unroll 4
    for (int d = 0; d < DIMK; d++) {
        ull xp0 = pk2(xs[nb][d], xs[nb][d]);
        ull xp1 = pk2(xs[nb + 1][d], xs[nb + 1][d]);
        ull xp2 = pk2(xs[nb + 2][d], xs[nb + 2][d]);
        ull xp3 = pk2(xs[nb + 3][d], xs[nb + 3][d]);
        #pragma unroll
        for (int r = 0; r < 5; r++) {
            ull wv = *(const ull*)(wp_ + (size_t)(r * DIMK + d) * H0K);
            acc[0][r] = fma2(wv, xp0, acc[0][r]);
            acc[1][r] = fma2(wv, xp1, acc[1][r]);
            acc[2][r] = fma2(wv, xp2, acc[2][r]);
            acc[3][r] = fma2(wv, xp3, acc[3][r]);
        }
    }
    #pragma unroll
    for (int i = 0; i < 4; i++)
        #pragma unroll
        for (int r = 0; r < 5; r++)
            *(ull*)&d_sup[((size_t)r * 4096 + n0 + nb + i) * H0K + 2 * h2] = acc[i][r];
}

// ---------------- pass A: double-buffered stream of 5 m-rows; emit code ----------------
__global__ void __launch_bounds__(256) k_passA(const int* __restrict__ u, const int* __restrict__ v,
                                               const float* __restrict__ m) {
    __shared__ float buf[2][ROWP];
    int tid = threadIdx.x;
    int i = blockIdx.x;
    int Ui = u[i];
    int vj[8];
    #pragma unroll
    for (int k = 0; k < 8; k++) vj[k] = v[tid + k * 256];
    int cls[8];
    #pragma unroll
    for (int k = 0; k < 8; k++) cls[k] = 255;

    uint32_t sb0 = s2u(buf[0]), sb1 = s2u(buf[1]);
    const size_t rstride = (size_t)NUSERS * NITEMS;
    const float* srcb = m + (size_t)Ui * NITEMS;

    // prologue: planes 0 and 1
    #pragma unroll
    for (int r = 0; r < 2; r++) {
        const float* src = srcb + r * rstride;
        uint32_t dst = r ? sb1 : sb0;
        for (int c = tid; c < 1853; c += 256)
            asm volatile("cp.async.ca.shared.global [%0], [%1], 8;"
                         :: "r"(dst + c * 8), "l"(src + c * 2));
        asm volatile("cp.async.commit_group;");
    }

    #pragma unroll
    for (int r = 0; r < RNC; r++) {
        if (r < 4) asm volatile("cp.async.wait_group 1;");
        else       asm volatile("cp.async.wait_group 0;");
        __syncthreads();
        const float* rows = buf[r & 1];
        #pragma unroll
        for (int k = 0; k < 8; k++)
            if (rows[vj[k]] > 0.5f) cls[k] = r;
        __syncthreads();
        if (r + 2 < RNC) {
            const float* src = srcb + (r + 2) * rstride;
            uint32_t dst = (r & 1) ? sb1 : sb0;   // buf[(r+2)&1] == buf[r&1]
            for (int c = tid; c < 1853; c += 256)
                asm volatile("cp.async.ca.shared.global [%0], [%1], 8;"
                             :: "r"(dst + c * 8), "l"(src + c * 2));
            asm volatile("cp.async.commit_group;");
        }
    }
    #pragma unroll
    for (int k = 0; k < 8; k++)
        d_code[(size_t)i * NVK + tid + k * 256] = (unsigned char)cls[k];
}

// ---------------- k_trans: build per-row edge lists (sup byte-offsets) + counts ----------------
__global__ void __launch_bounds__(256) k_trans() {
    __shared__ unsigned char tsm[32][40];
    int tid = threadIdx.x;
    int r = tid >> 3, l = tid & 7;
    unsigned bx = blockIdx.x * 32, by = blockIdx.y * 32;   // bx: v, by: u
    uchar4 val = *(const uchar4*)(d_code + (size_t)(by + r) * NVK + bx + l * 4);
    tsm[l * 4 + 0][r] = val.x; tsm[l * 4 + 1][r] = val.y;
    tsm[l * 4 + 2][r] = val.z; tsm[l * 4 + 3][r] = val.w;

    // side A: u-row lists (edges point to sup item rows)
    {
        int cx = val.x < 5, cy = val.y < 5, cz = val.z < 5, cw = val.w < 5;
        int cnt = cx + cy + cz + cw;
        int p = cnt;
        #pragma unroll
        for (int off = 1; off < 8; off <<= 1) {
            int t = __shfl_up_sync(0xffffffffu, p, off, 8);
            if (l >= off) p += t;
        }
        int tot = __shfl_sync(0xffffffffu, p, 7, 8);
        int base = 0;
        if (l == 0 && tot) base = atomicAdd(&d_cntU[by + r], tot);
        base = __shfl_sync(0xffffffffu, base, 0, 8);
        int pos = base + p - cnt;
        unsigned* dst = d_elistU + (size_t)(by + r) * CAP;
        unsigned vb8 = (2048u + bx + l * 4) << 8;
        if (cx) { if (pos < CAP) dst[pos] = ((unsigned)val.x << 20) + vb8;        pos++; }
        if (cy) { if (pos < CAP) dst[pos] = ((unsigned)val.y << 20) + vb8 + 256;  pos++; }
        if (cz) { if (pos < CAP) dst[pos] = ((unsigned)val.z << 20) + vb8 + 512;  pos++; }
        if (cw) { if (pos < CAP) dst[pos] = ((unsigned)val.w << 20) + vb8 + 768;  pos++; }
    }
    __syncthreads();
    // side B: v-row lists (edges point to sup user rows)
    {
        uchar4 tv = *(const uchar4*)&tsm[r][l * 4];
        int cx = tv.x < 5, cy = tv.y < 5, cz = tv.z < 5, cw = tv.w < 5;
        int cnt = cx + cy + cz + cw;
        int p = cnt;
        #pragma unroll
        for (int off = 1; off < 8; off <<= 1) {
            int t = __shfl_up_sync(0xffffffffu, p, off, 8);
            if (l >= off) p += t;
        }
        int tot = __shfl_sync(0xffffffffu, p, 7, 8);
        int base = 0;
        if (l == 0 && tot) base = atomicAdd(&d_cntV[bx + r], tot);
        base = __shfl_sync(0xffffffffu, base, 0, 8);
        int pos = base + p - cnt;
        unsigned* dst = d_elistV + (size_t)(bx + r) * CAP;
        unsigned ub8 = (by + l * 4) << 8;
        if (cx) { if (pos < CAP) dst[pos] = ((unsigned)tv.x << 20) + ub8;        pos++; }
        if (cy) { if (pos < CAP) dst[pos] = ((unsigned)tv.y << 20) + ub8 + 256;  pos++; }
        if (cz) { if (pos < CAP) dst[pos] = ((unsigned)tv.z << 20) + ub8 + 512;  pos++; }
        if (cw) { if (pos < CAP) dst[pos] = ((unsigned)tv.w << 20) + ub8 + 768;  pos++; }
    }
}

// ---------------- k_rows: list gather + dense + sigmoid + t ----------------
__global__ void __launch_bounds__(64) k_rows(const float* __restrict__ gclb, const float* __restrict__ dw,
                                             const float* __restrict__ db, const float* __restrict__ P) {
    int n = blockIdx.x;
    int tid = threadIdx.x, lane = tid & 31, w = tid >> 5;
    __shared__ ull accs[32];
    __shared__ float zs[H0K];
    __shared__ float hid[H1K];

    const unsigned* list; int cnt; float deg;
    if (n < NUK) { list = d_elistU + (size_t)n * CAP; cnt = d_cntU[n]; deg = (float)d_cntV[n]; }
    else { int k2 = n - NUK; list = d_elistV + (size_t)k2 * CAP; cnt = d_cntV[k2]; deg = (float)d_cntU[k2]; }
    if (cnt > CAP) cnt = CAP;

    int half = (cnt + 1) >> 1;
    int s = w ? half : 0, e = w ? cnt : half;
    ull one2 = pk2(1.f, 1.f);
    ull a0 = 0ull, a1 = 0ull, a2 = 0ull, a3 = 0ull;
    const char* supb = (const char*)d_sup;
    for (int k0 = s; k0 < e; k0 += 32) {
        unsigned ent = (k0 + lane < e) ? list[k0 + lane] : 0u;
        int nb = min(32, e - k0);
        int it = 0;
        for (; it + 4 <= nb; it += 4) {
            unsigned o0 = __shfl_sync(0xffffffffu, ent, it);
            unsigned o1 = __shfl_sync(0xffffffffu, ent, it + 1);
            unsigned o2 = __shfl_sync(0xffffffffu, ent, it + 2);
            unsigned o3 = __shfl_sync(0xffffffffu, ent, it + 3);
            ull p0 = *(const ull*)(supb + o0 + lane * 8);
            ull p1 = *(const ull*)(supb + o1 + lane * 8);
            ull p2 = *(const ull*)(supb + o2 + lane * 8);
            ull p3 = *(const ull*)(supb + o3 + lane * 8);
            a0 = fma2(p0, one2, a0);
            a1 = fma2(p1, one2, a1);
            a2 = fma2(p2, one2, a2);
            a3 = fma2(p3, one2, a3);
        }
        for (; it < nb; it++) {
            unsigned o0 = __shfl_sync(0xffffffffu, ent, it);
            a0 = fma2(*(const ull*)(supb + o0 + lane * 8), one2, a0);
        }
    }
    ull acc = fma2(a0, one2, a1);
    ull acb = fma2(a2, one2, a3);
    acc = fma2(acc, one2, acb);

    if (w == 1) accs[lane] = acc;
    __syncthreads();
    if (w == 0) {
        acc = fma2(accs[lane], one2, acc);
        float f0, f1; upk2(acc, f0, f1);
        float cinv = (deg > 0.f) ? (1.f / deg) : 0.f;
        float z0 = fmaf(f0, cinv, 5.f * gclb[2 * lane]);
        float z1 = fmaf(f1, cinv, 5.f * gclb[2 * lane + 1]);
        zs[2 * lane]     = fmaxf(z0, 0.f);
        zs[2 * lane + 1] = fmaxf(z1, 0.f);
    }
    __syncthreads();
    if (tid < H1K) {
        float sacc = db[tid];
        #pragma unroll
        for (int h0 = 0; h0 < H0K; h0++) sacc = fmaf(zs[h0], dw[h0 * H1K + tid], sacc);
        float hv = 1.f / (1.f + fexp(-sacc));
        d_hidden[n * H1K + tid] = hv;
        hid[tid] = hv;
    }
    __syncthreads();
    if (n < NUK) {
        int b = tid >> 5, ei = tid & 31;
        float t = 0.f;
        #pragma unroll
        for (int d = 0; d < H1K; d++) t = fmaf(hid[d], P[((size_t)b * H1K + d) * H1K + ei], t);
        d_t[(size_t)n * 64 + ei * 2 + b] = t;
    }
}

// ---------------- k_final: rank-2 logits, shifted softmax, m_hat, loss, rmse, finalize ----------------
__global__ void __launch_bounds__(256) k_final(float* __restrict__ out, int out_size) {
    __shared__ float st[32 * 64];
    __shared__ float shv[32 * 33];
    __shared__ unsigned char scd[1024];
    __shared__ float red[16];
    __shared__ int slast;
    int tid = threadIdx.x;
    int ub = blockIdx.y * 32, vb = blockIdx.x * 32;

    for (int idx = tid; idx < 2048; idx += 256) st[idx] = d_t[(size_t)ub * 64 + idx];
    for (int idx = tid; idx < 1024; idx += 256)
        shv[(idx >> 5) * 33 + (idx & 31)] = d_hidden[(size_t)(NUK + vb + (idx >> 5)) * H1K + (idx & 31)];
    {
        int row = tid >> 3, c4 = (tid & 7) * 4;
        *(uchar4*)(scd + row * 32 + c4) = *(const uchar4*)(d_code + (size_t)(ub + row) * NVK + vb + c4);
    }
    ull B12a = *(const ull*)&d_b8[0];   // (b10,b20)
    ull B12b = *(const ull*)&d_b8[2];   // (b11,b21)
    ull B34a = *(const ull*)&d_b8[4];
    ull B34b = *(const ull*)&d_b8[6];
    __syncthreads();

    int u0 = (tid >> 4) * 2, v0 = (tid & 15) * 2;
    float hva[32], hvb[32];
    #pragma unroll
    for (int e = 0; e < 32; e++) { hva[e] = shv[v0 * 33 + e]; hvb[e] = shv[(v0 + 1) * 33 + e]; }

    ull acc[4] = {0ull, 0ull, 0ull, 0ull};
    const float* t0 = st + u0 * 64;
    const float* t1 = t0 + 64;
    #pragma unroll
    for (int e = 0; e < 32; e++) {
        ull ta = *(const ull*)(t0 + e * 2);
        ull tb = *(const ull*)(t1 + e * 2);
        ull hap = pk2(hva[e], hva[e]);
        ull hbp = pk2(hvb[e], hvb[e]);
        acc[0] = fma2(ta, hap, acc[0]);
        acc[1] = fma2(ta, hbp, acc[1]);
        acc[2] = fma2(tb, hap, acc[2]);
        acc[3] = fma2(tb, hbp, acc[3]);
    }

    const ull K23 = 0x4040000040000000ull;   // (2,3)
    const ull K45 = 0x40A0000040800000ull;   // (4,5)
    float loss_t = 0.f, rmse_t = 0.f;
    float mh[4];
    #pragma unroll
    for (int p = 0; p < 4; p++) {
        float s0, s1; upk2(acc[p], s0, s1);
        ull s0x = pk2(s0, s0), s1x = pk2(s1, s1);
        ull D12 = fma2(B12a, s0x, mul2(B12b, s1x));   // (d1,d2)
        ull D34 = fma2(B34a, s0x, mul2(B34b, s1x));   // (d3,d4)
        ull E12 = fexp2(D12);
        ull E34 = fexp2(D34);
        float e1, e2, e3, e4;
        upk2(E12, e1, e2); upk2(E34, e3, e4);
        float S = 1.f + ((e1 + e2) + (e3 + e4));
        ull N2 = fma2(E34, K45, mul2(E12, K23));
        float n1, n2; upk2(N2, n1, n2);
        float num = 1.f + (n1 + n2);
        float inv; asm("rcp.approx.f32 %0,%1;" : "=f"(inv) : "f"(S));
        inv = inv * fmaf(-S, inv, 2.0f);
        float m_hat = num * inv;
        mh[p] = m_hat;
        int du_ = p >> 1, dv_ = p & 1;
        unsigned char c = scd[(u0 + du_) * 32 + (v0 + dv_)];
        if (c < 5) {
            float d1, d2, d3, d4;
            upk2(D12, d1, d2); upk2(D34, d3, d4);
            float dc = 0.f;
            dc = (c == 1) ? d1 : dc; dc = (c == 2) ? d2 : dc;
            dc = (c == 3) ? d3 : dc; dc = (c == 4) ? d4 : dc;
            loss_t += __logf(S) - dc;
            float dd = m_hat - (float)(c + 1);
            rmse_t = fmaf(dd, dd, rmse_t);
        }
    }
    {
        size_t base = (size_t)(ub + u0) * NVK + vb + v0;
        *(float2*)(out + base)       = make_float2(mh[0], mh[1]);
        *(float2*)(out + base + NVK) = make_float2(mh[2], mh[3]);
    }
    #pragma unroll
    for (int o = 16; o > 0; o >>= 1) {
        loss_t += __shfl_down_sync(0xffffffffu, loss_t, o);
        rmse_t += __shfl_down_sync(0xffffffffu, rmse_t, o);
    }
    int lane = tid & 31, w = tid >> 5;
    if (lane == 0) { red[w] = loss_t; red[8 + w] = rmse_t; }
    __syncthreads();
    if (tid == 0) {
        float ls = 0.f, rs = 0.f;
        #pragma unroll
        for (int q = 0; q < 8; q++) { ls += red[q]; rs += red[8 + q]; }
        atomicAdd(&d_acc2[0], ls);
        atomicAdd(&d_acc2[1], rs);
        __threadfence();
        unsigned t = atomicAdd(&d_ticket, 1u);
        slast = (t == 4095u);
    }
    __syncthreads();
    if (slast) {
        int s = 0;
        for (int idx = tid; idx < NVK; idx += 256) s += d_cntV[idx];
        #pragma unroll
        for (int o = 16; o > 0; o >>= 1) s += __shfl_down_sync(0xffffffffu, s, o);
        if (lane == 0) red[w] = (float)s;
        __syncthreads();
        if (tid == 0) {
            float cnt = 0.f;
            #pragma unroll
            for (int q = 0; q < 8; q++) cnt += red[q];
            cnt = fmaxf(cnt, 1.f);
            float ls = atomicAdd(&d_acc2[0], 0.f);
            float rs = atomicAdd(&d_acc2[1], 0.f);
            out[out_size - 2] = ls / cnt;
            out[out_size - 1] = sqrtf(rs / cnt);
        }
    }
}

extern "C" void kernel_launch(void* const* d_in, const int* in_sizes, int n_in,
                              void* d_out, int out_size) {
    const int*   u       = (const int*)d_in[0];
    const int*   v       = (const int*)d_in[1];
    const float* m       = (const float*)d_in[2];
    const float* u_emb   = (const float*)d_in[3];
    const float* v_emb   = (const float*)d_in[4];
    const float* gcl_w   = (const float*)d_in[5];
    const float* gcl_b   = (const float*)d_in[6];
    const float* dense_w = (const float*)d_in[7];
    const float* dense_b = (const float*)d_in[8];
    const float* P       = (const float*)d_in[9];
    const float* a       = (const float*)d_in[10];
    float* out = (float*)d_out;

    k_sup<<<257, 128>>>(u, v, u_emb, v_emb, gcl_w, a);
    k_passA<<<2048, 256>>>(u, v, m);
    k_trans<<<dim3(64, 64), 256>>>();
    k_rows<<<4096, 64>>>(gcl_b, dense_w, dense_b, P);
    k_final<<<dim3(64, 64), 256>>>(out, out_size);
}